// round 15
// baseline (speedup 1.0000x reference)
#include <cuda_runtime.h>
#include <cstdint>
#include <math.h>

// Problem constants
#define Bn   4
#define Sn   2048
#define Dn   1024
#define Hn   16
#define DHn  64
#define BHn  (Bn * Hn)          // 64
#define Mn   (Bn * Sn)          // 8192
#define NQT  (Sn / 128)         // 16 q-tiles
#define SCALE_F 0.125f

#define OUT_ELEMS  ((size_t)Mn * Dn)            // 8,388,608
#define ATTN_ELEMS ((size_t)BHn * Sn * Sn)      // 268,435,456

// Scratch (device globals)
__device__ float g_q[Mn * Dn];            // [B,H,S,DH] tf32-rounded, DH pi-permuted
__device__ float g_k[Mn * Dn];
__device__ float g_v[Mn * Dn];
__device__ float g_ctx[Mn * Dn];          // [B,S,H*DH] tf32-rounded, pi-permuted
__device__ float g_qc[Mn * Dn];           // tf32-rounded + k-permuted inputs
__device__ float g_kc[Mn * Dn];
__device__ float g_vc[Mn * Dn];
__device__ float g_wc[4][Dn * Dn];        // weights: transposed [N,K], tf32, k-permuted
__device__ float g_attn_scratch[ATTN_ELEMS];

// ---------------------------------------------------------------------------
// PTX helpers
// ---------------------------------------------------------------------------
__device__ __forceinline__ uint32_t smem_u32(const void* p) {
    uint32_t a;
    asm("{ .reg .u64 t; cvta.to.shared.u64 t, %1; cvt.u32.u64 %0, t; }" : "=r"(a) : "l"(p));
    return a;
}
#define CP16(dst, src) \
    asm volatile("cp.async.cg.shared.global [%0], [%1], 16;" :: "r"(dst), "l"(src))
#define CP_COMMIT() asm volatile("cp.async.commit_group;")
#define CP_WAIT1()  asm volatile("cp.async.wait_group 1;")
#define CP_WAIT0()  asm volatile("cp.async.wait_group 0;")

__device__ __forceinline__ float tf32r(float f) {
    uint32_t r; asm("cvt.rna.tf32.f32 %0, %1;" : "=r"(r) : "f"(f));
    return __uint_as_float(r);
}
__device__ __forceinline__ void mma_tf32(float c[4], const uint32_t a[4], const uint32_t b[2]) {
    asm volatile(
        "mma.sync.aligned.m16n8k8.row.col.f32.tf32.tf32.f32 "
        "{%0,%1,%2,%3}, {%4,%5,%6,%7}, {%8,%9}, {%0,%1,%2,%3};"
        : "+f"(c[0]), "+f"(c[1]), "+f"(c[2]), "+f"(c[3])
        : "r"(a[0]), "r"(a[1]), "r"(a[2]), "r"(a[3]), "r"(b[0]), "r"(b[1]));
}
__device__ __forceinline__ uint32_t fbits(float f) { return __float_as_uint(f); }
// pi: logical l (0..7) -> physical slot. phys(2i)=l_i, phys(2i+1)=l_{i+4}
__device__ __forceinline__ int pkmap(int l) { return (l < 4) ? (2 * l) : (2 * (l - 4) + 1); }

// ---------------------------------------------------------------------------
// round + k-permute, 3 tensors in one launch (grid.z selects)
// ---------------------------------------------------------------------------
__global__ __launch_bounds__(256) void round_perm3_kernel(
    const float* __restrict__ i0, const float* __restrict__ i1, const float* __restrict__ i2,
    float* __restrict__ o0, float* __restrict__ o1, float* __restrict__ o2, int n8)
{
    const int z = blockIdx.z;
    const float* in = (z == 0) ? i0 : (z == 1) ? i1 : i2;
    float* out      = (z == 0) ? o0 : (z == 1) ? o1 : o2;
    int i = blockIdx.x * 256 + threadIdx.x;
    if (i < n8) {
        const float4* p = (const float4*)in + (size_t)i * 2;
        float4 a = p[0], b = p[1];
        float4 q0 = make_float4(tf32r(a.x), tf32r(b.x), tf32r(a.y), tf32r(b.y));
        float4 q1 = make_float4(tf32r(a.z), tf32r(b.z), tf32r(a.w), tf32r(b.w));
        float4* q = (float4*)out + (size_t)i * 2;
        q[0] = q0; q[1] = q1;
    }
}

// ---------------------------------------------------------------------------
// weight transpose x4: W[K,N] -> Wt[N,K], tf32-rounded, k pi-permuted
// ---------------------------------------------------------------------------
__global__ __launch_bounds__(256) void wtrans4_kernel(
    const float* __restrict__ i0, const float* __restrict__ i1,
    const float* __restrict__ i2, const float* __restrict__ i3,
    float* __restrict__ o0, float* __restrict__ o1,
    float* __restrict__ o2, float* __restrict__ o3)
{
    const int z = blockIdx.z;
    const float* in = (z == 0) ? i0 : (z == 1) ? i1 : (z == 2) ? i2 : i3;
    float* out      = (z == 0) ? o0 : (z == 1) ? o1 : (z == 2) ? o2 : o3;
    __shared__ float tile[32][33];
    int tx = threadIdx.x, ty = threadIdx.y;
    int k0 = blockIdx.y * 32, n0 = blockIdx.x * 32;
#pragma unroll
    for (int j = 0; j < 32; j += 8)
        tile[ty + j][tx] = in[(size_t)(k0 + ty + j) * Dn + n0 + tx];
    __syncthreads();
    int pk = (tx & ~7) | pkmap(tx & 7);
#pragma unroll
    for (int j = 0; j < 32; j += 8)
        out[(size_t)(n0 + ty + j) * Dn + k0 + pk] = tf32r(tile[tx][ty + j]);
}

// ---------------------------------------------------------------------------
// tf32 mma GEMM: out = X[M,1024] @ Wt[N,K]^T + bias. 2-stage, 2 CTAs/SM.
// X and Wt are pre-rounded + k-permuted -> LDS.64 fragments, no cvt.
// ---------------------------------------------------------------------------
#define G_AST 40
#define G_STAGE_F (128 * G_AST * 2)          // 10240 floats
#define GEMM_SMEM (2 * G_STAGE_F * 4)        // 81,920 bytes

__global__ __launch_bounds__(256, 2) void tf32_gemm_kernel(
    const float* __restrict__ X0, const float* __restrict__ X1, const float* __restrict__ X2,
    const float* __restrict__ W0, const float* __restrict__ W1, const float* __restrict__ W2,
    const float* __restrict__ B0, const float* __restrict__ B1, const float* __restrict__ B2,
    float* __restrict__ O0, float* __restrict__ O1, float* __restrict__ O2,
    int mode)
{
    extern __shared__ float sm[];
    const int z = blockIdx.z;
    const float* X    = (z == 0) ? X0 : (z == 1) ? X1 : X2;
    const float* W    = (z == 0) ? W0 : (z == 1) ? W1 : W2;
    const float* bias = (z == 0) ? B0 : (z == 1) ? B1 : B2;
    float* out        = (z == 0) ? O0 : (z == 1) ? O1 : O2;

    const int tid = threadIdx.x;
    const int wid = tid >> 5, lane = tid & 31;
    const int g = lane >> 2, t = lane & 3;
    const int warpM = wid & 1, warpN = wid >> 1;
    const int bm = blockIdx.y * 128, bn = blockIdx.x * 128;

    const uint32_t sbase = smem_u32(sm);

    float c[4][4][4];
#pragma unroll
    for (int i = 0; i < 4; i++)
#pragma unroll
        for (int j = 0; j < 4; j++)
#pragma unroll
            for (int k = 0; k < 4; k++) c[i][j][k] = 0.0f;

    auto issue = [&](int cidx, int buf) {
        const float* Xp = X + (size_t)bm * Dn + cidx * 32;
        const float* Wp = W + (size_t)bn * Dn + cidx * 32;   // Wt[N,K]
        uint32_t abase = sbase + buf * (G_STAGE_F * 4);
        uint32_t bbase = abase + 128 * G_AST * 4;
#pragma unroll
        for (int j = 0; j < 4; j++) {
            int ia = tid + j * 256;
            int r = ia >> 3, cc = ia & 7;
            CP16(abase + r * (G_AST * 4) + cc * 16, Xp + (size_t)r * Dn + cc * 4);
            CP16(bbase + r * (G_AST * 4) + cc * 16, Wp + (size_t)r * Dn + cc * 4);
        }
    };

    issue(0, 0); CP_COMMIT();

    const int NCH = Dn / 32;   // 32
    for (int s = 0; s < NCH; s++) {
        CP_WAIT0();
        __syncthreads();
        if (s + 1 < NCH) { issue(s + 1, (s + 1) & 1); CP_COMMIT(); }

        const float* A = sm + (s & 1) * G_STAGE_F;
        const float* B = A + 128 * G_AST;
#pragma unroll
        for (int kk = 0; kk < 32; kk += 8) {
            uint32_t af[4][4], bf[4][2];
#pragma unroll
            for (int mt = 0; mt < 4; mt++) {
                int r0 = warpM * 64 + mt * 16 + g;
                float2 a0 = *(const float2*)&A[r0 * G_AST + kk + 2 * t];
                float2 a1 = *(const float2*)&A[(r0 + 8) * G_AST + kk + 2 * t];
                af[mt][0] = fbits(a0.x); af[mt][1] = fbits(a1.x);
                af[mt][2] = fbits(a0.y); af[mt][3] = fbits(a1.y);
            }
#pragma unroll
            for (int nt = 0; nt < 4; nt++) {
                int n0 = warpN * 32 + nt * 8 + g;
                float2 bv = *(const float2*)&B[n0 * G_AST + kk + 2 * t];
                bf[nt][0] = fbits(bv.x); bf[nt][1] = fbits(bv.y);
            }
#pragma unroll
            for (int mt = 0; mt < 4; mt++)
#pragma unroll
                for (int nt = 0; nt < 4; nt++)
                    mma_tf32(c[mt][nt], af[mt], bf[nt]);
        }
    }

#pragma unroll
    for (int mt = 0; mt < 4; mt++) {
#pragma unroll
        for (int nt = 0; nt < 4; nt++) {
            int m0 = bm + warpM * 64 + mt * 16 + g;
            int n0 = bn + warpN * 32 + nt * 8 + 2 * t;
#pragma unroll
            for (int half = 0; half < 2; half++) {
                int m = m0 + half * 8;
                float v0 = c[mt][nt][half * 2 + 0] + bias[n0];
                float v1 = c[mt][nt][half * 2 + 1] + bias[n0 + 1];
                if (mode == 0) {
                    out[(size_t)m * Dn + n0] = v0;
                    out[(size_t)m * Dn + n0 + 1] = v1;
                } else {
                    // head layout, d pi-permuted within 8-groups (consumers read raw)
                    int b = m >> 11, sq = m & (Sn - 1);
                    int h = n0 >> 6;
                    int np0 = (n0 & ~7) | pkmap(n0 & 7);
                    int np1 = (n0 & ~7) | pkmap((n0 & 7) + 1);
                    size_t base = (((size_t)b * Hn + h) * Sn + sq) * DHn;
                    out[base + (np0 & 63)] = tf32r(v0);
                    out[base + (np1 & 63)] = tf32r(v1);
                }
            }
        }
    }
}

// ---------------------------------------------------------------------------
// Fused attention, 2 CTAs/SM. Q/K DH pi-permuted -> LDS.64 QK fragments.
// Ps stored pi-permuted along key dim -> LDS.64 PV A-fragments; attn store
// un-permutes in registers. P stored fp32 (mma truncates; attn more precise).
// ---------------------------------------------------------------------------
#define FQ_ST 72
#define FK_ST 72
#define FV_ST 72
#define FP_ST 72
#define F_Q    0                          // 128 x 72
#define F_A    (128 * FQ_ST)              // 64 x 72
#define F_B    (F_A + 64 * FK_ST)         // 64 x 72
#define F_P    (F_B + 64 * FK_ST)         // 128 x 72
#define F_L    (F_P + 128 * FP_ST)        // 128
#define F_INV  (F_L + 128)                // 128
#define FUSED_SMEM ((F_INV + 128) * 4)    // 111,616 bytes

__global__ __launch_bounds__(256, 2) void fused_attn_kernel(
    const float* __restrict__ q, const float* __restrict__ k,
    const float* __restrict__ v, float* __restrict__ attn,
    float* __restrict__ ctx)
{
    extern __shared__ float sm[];
    const int bh = blockIdx.y;
    const int qt = (NQT - 1) - blockIdx.x;   // heavy tiles first
    const int b = bh >> 4, h = bh & 15;

    const int tid = threadIdx.x;
    const int wid = tid >> 5, lane = tid & 31;
    const int g = lane >> 2, t = lane & 3;
    const int warpM = wid & 1, warpN = wid >> 1;   // 2 x 4

    const uint32_t sbase = smem_u32(sm);
    const float* qb = q + ((size_t)bh * Sn + qt * 128) * DHn;
    const float* kbase = k + (size_t)bh * Sn * DHn;
    const float* vbase = v + (size_t)bh * Sn * DHn;
    float* attn_base = attn + ((size_t)bh * Sn + qt * 128) * Sn;

    const int ntiles = 2 * (qt + 1);   // 64-row K/V tiles

    auto issueK = [&](int c, uint32_t bufoff) {
        const float* kb = kbase + (size_t)(c * 64) * DHn;
        uint32_t dst = sbase + bufoff * 4;
#pragma unroll
        for (int j = 0; j < 4; j++) {
            int ia = tid + j * 256;
            int r = ia >> 4, c4 = ia & 15;
            CP16(dst + r * (FK_ST * 4) + c4 * 16, kb + (size_t)r * DHn + c4 * 4);
        }
    };
    auto issueV = [&](int c, uint32_t bufoff) {
        const float* vb = vbase + (size_t)(c * 64) * DHn;
        uint32_t dst = sbase + bufoff * 4;
#pragma unroll
        for (int j = 0; j < 4; j++) {
            int ia = tid + j * 256;
            int r = ia >> 4, c4 = ia & 15;
            CP16(dst + r * (FV_ST * 4) + c4 * 16, vb + (size_t)r * DHn + c4 * 4);
        }
    };

    // Q load + first K tile
    {
        uint32_t qdst = sbase + F_Q * 4;
#pragma unroll
        for (int j = 0; j < 8; j++) {
            int ia = tid + j * 256;
            int r = ia >> 4, c4 = ia & 15;
            CP16(qdst + r * (FQ_ST * 4) + c4 * 16, qb + (size_t)r * DHn + c4 * 4);
        }
        issueK(0, F_A);
        CP_COMMIT();
    }

    // zero-fill causal upper region (overlaps async loads)
    {
        int zc0 = (qt + 1) * 128;
        int nz4 = (Sn - zc0) >> 2;
        if (nz4 > 0) {
            const float4 zz = make_float4(0.f, 0.f, 0.f, 0.f);
            for (int idx = tid; idx < 128 * nz4; idx += 256) {
                int r = idx / nz4, cc = idx - r * nz4;
                *(float4*)(attn_base + (size_t)r * Sn + zc0 + cc * 4) = zz;
            }
        }
    }

    if (tid < 128) sm[F_L + tid] = 0.0f;

    const float* Qs = sm + F_Q;

    // ---------------- Phase 1: row sums of exp(S) ----------------
    float rs[8];
#pragma unroll
    for (int i = 0; i < 8; i++) rs[i] = 0.0f;

    for (int c = 0; c < ntiles; c++) {
        CP_WAIT0();
        __syncthreads();
        if (c + 1 < ntiles) {
            issueK(c + 1, ((c + 1) & 1) ? F_B : F_A);
            CP_COMMIT();
        }

        const float* K = sm + ((c & 1) ? F_B : F_A);
        float cs[4][2][4];
#pragma unroll
        for (int i = 0; i < 4; i++)
#pragma unroll
            for (int j = 0; j < 2; j++)
#pragma unroll
                for (int kk = 0; kk < 4; kk++) cs[i][j][kk] = 0.0f;

#pragma unroll
        for (int kk = 0; kk < 64; kk += 8) {
            uint32_t af[4][4], bf[2][2];
#pragma unroll
            for (int mt = 0; mt < 4; mt++) {
                int r0 = warpM * 64 + mt * 16 + g;
                float2 a0 = *(const float2*)&Qs[r0 * FQ_ST + kk + 2 * t];
                float2 a1 = *(const float2*)&Qs[(r0 + 8) * FQ_ST + kk + 2 * t];
                af[mt][0] = fbits(a0.x); af[mt][1] = fbits(a1.x);
                af[mt][2] = fbits(a0.y); af[mt][3] = fbits(a1.y);
            }
#pragma unroll
            for (int nt = 0; nt < 2; nt++) {
                int n0 = warpN * 16 + nt * 8 + g;
                float2 bv = *(const float2*)&K[n0 * FK_ST + kk + 2 * t];
                bf[nt][0] = fbits(bv.x); bf[nt][1] = fbits(bv.y);
            }
#pragma unroll
            for (int mt = 0; mt < 4; mt++)
#pragma unroll
                for (int nt = 0; nt < 2; nt++)
                    mma_tf32(cs[mt][nt], af[mt], bf[nt]);
        }

        if (c < 2 * qt) {
#pragma unroll
            for (int mt = 0; mt < 4; mt++)
#pragma unroll
                for (int half = 0; half < 2; half++) {
                    float acc = 0.0f;
#pragma unroll
                    for (int nt = 0; nt < 2; nt++) {
                        acc += __expf(cs[mt][nt][half * 2] * SCALE_F);
                        acc += __expf(cs[mt][nt][half * 2 + 1] * SCALE_F);
                    }
                    rs[mt * 2 + half] += acc;
                }
        } else {
#pragma unroll
            for (int mt = 0; mt < 4; mt++)
#pragma unroll
                for (int half = 0; half < 2; half++) {
                    int qi = qt * 128 + warpM * 64 + mt * 16 + g + half * 8;
                    float acc = 0.0f;
#pragma unroll
                    for (int nt = 0; nt < 2; nt++) {
                        int kj = c * 64 + warpN * 16 + nt * 8 + 2 * t;
                        if (kj <= qi)     acc += __expf(cs[mt][nt][half * 2] * SCALE_F);
                        if (kj + 1 <= qi) acc += __expf(cs[mt][nt][half * 2 + 1] * SCALE_F);
                    }
                    rs[mt * 2 + half] += acc;
                }
        }
    }

    // prefetch phase-2 tiles, then reduce row sums
    __syncthreads();
    issueK(0, F_A); CP_COMMIT();
    issueV(0, F_B); CP_COMMIT();

#pragma unroll
    for (int i = 0; i < 8; i++) {
        rs[i] += __shfl_xor_sync(0xffffffffu, rs[i], 1);
        rs[i] += __shfl_xor_sync(0xffffffffu, rs[i], 2);
    }
    if (t == 0) {
#pragma unroll
        for (int i = 0; i < 8; i++) {
            int row = warpM * 64 + (i >> 1) * 16 + g + (i & 1) * 8;
            atomicAdd(&sm[F_L + row], rs[i]);
        }
    }
    __syncthreads();
    if (tid < 128) sm[F_INV + tid] = 1.0f / sm[F_L + tid];
    __syncthreads();

    // ---------------- Phase 2: attn write + P@V (pi-layout Ps) ----------------
    float o[4][2][4];
#pragma unroll
    for (int i = 0; i < 4; i++)
#pragma unroll
        for (int j = 0; j < 2; j++)
#pragma unroll
            for (int kk = 0; kk < 4; kk++) o[i][j][kk] = 0.0f;

    float* Ps = sm + F_P;
    const float* invl = sm + F_INV;
    const float* Kb = sm + F_A;
    const float* Vb = sm + F_B;

    // exp-epilogue physical store offsets within the 8-group
    const int pp0 = pkmap(2 * t);       // physical slot of logical col 2t
    const int pp1 = pkmap(2 * t + 1);   // physical slot of logical col 2t+1

    // attn store mapping: thread handles 8-col group gi of rows r0+32j
    const int st_gi = tid & 7, st_r0 = tid >> 3;

    for (int c = 0; c < ntiles; c++) {
        CP_WAIT1();
        __syncthreads();

        float cs[4][2][4];
#pragma unroll
        for (int i = 0; i < 4; i++)
#pragma unroll
            for (int j = 0; j < 2; j++)
#pragma unroll
                for (int kk = 0; kk < 4; kk++) cs[i][j][kk] = 0.0f;

#pragma unroll
        for (int kk = 0; kk < 64; kk += 8) {
            uint32_t af[4][4], bf[2][2];
#pragma unroll
            for (int mt = 0; mt < 4; mt++) {
                int r0 = warpM * 64 + mt * 16 + g;
                float2 a0 = *(const float2*)&Qs[r0 * FQ_ST + kk + 2 * t];
                float2 a1 = *(const float2*)&Qs[(r0 + 8) * FQ_ST + kk + 2 * t];
                af[mt][0] = fbits(a0.x); af[mt][1] = fbits(a1.x);
                af[mt][2] = fbits(a0.y); af[mt][3] = fbits(a1.y);
            }
#pragma unroll
            for (int nt = 0; nt < 2; nt++) {
                int n0 = warpN * 16 + nt * 8 + g;
                float2 bv = *(const float2*)&Kb[n0 * FK_ST + kk + 2 * t];
                bf[nt][0] = fbits(bv.x); bf[nt][1] = fbits(bv.y);
            }
#pragma unroll
            for (int mt = 0; mt < 4; mt++)
#pragma unroll
                for (int nt = 0; nt < 2; nt++)
                    mma_tf32(cs[mt][nt], af[mt], bf[nt]);
        }

        __syncthreads();
        if (c + 1 < ntiles) { issueK(c + 1, F_A); CP_COMMIT(); }

        // P = exp(S)*inv_l (fp32) -> smem Ps at pi-physical positions
        if (c < 2 * qt) {
#pragma unroll
            for (int mt = 0; mt < 4; mt++)
#pragma unroll
                for (int half = 0; half < 2; half++) {
                    int rloc = warpM * 64 + mt * 16 + g + half * 8;
                    float inv = invl[rloc];
#pragma unroll
                    for (int nt = 0; nt < 2; nt++) {
                        int gb = warpN * 16 + nt * 8;
                        float p0 = __expf(cs[mt][nt][half * 2] * SCALE_F) * inv;
                        float p1 = __expf(cs[mt][nt][half * 2 + 1] * SCALE_F) * inv;
                        Ps[rloc * FP_ST + gb + pp0] = p0;
                        Ps[rloc * FP_ST + gb + pp1] = p1;
                    }
                }
        } else {
#pragma unroll
            for (int mt = 0; mt < 4; mt++)
#pragma unroll
                for (int half = 0; half < 2; half++) {
                    int rloc = warpM * 64 + mt * 16 + g + half * 8;
                    int qi = qt * 128 + rloc;
                    float inv = invl[rloc];
#pragma unroll
                    for (int nt = 0; nt < 2; nt++) {
                        int gb = warpN * 16 + nt * 8;
                        int kj = c * 64 + gb + 2 * t;
                        float p0 = (kj <= qi) ? __expf(cs[mt][nt][half * 2] * SCALE_F) * inv : 0.0f;
                        float p1 = (kj + 1 <= qi) ? __expf(cs[mt][nt][half * 2 + 1] * SCALE_F) * inv : 0.0f;
                        Ps[rloc * FP_ST + gb + pp0] = p0;
                        Ps[rloc * FP_ST + gb + pp1] = p1;
                    }
                }
        }

        // V(c) ready
        if (c + 1 < ntiles) CP_WAIT1(); else CP_WAIT0();
        __syncthreads();   // Ps visible + V ready

        // attn store: un-permute pi-layout in registers, coalesced float4 x2
        {
            float* dst = attn_base + c * 64 + st_gi * 8;
#pragma unroll
            for (int j = 0; j < 4; j++) {
                int r = st_r0 + j * 32;
                const float* src = &Ps[r * FP_ST + st_gi * 8];
                float4 A4 = *(const float4*)src;
                float4 B4 = *(const float4*)(src + 4);
                float* d = dst + (size_t)r * Sn;
                *(float4*)d       = make_float4(A4.x, A4.z, B4.x, B4.z);
                *(float4*)(d + 4) = make_float4(A4.y, A4.w, B4.y, B4.w);
            }
        }

        // O += P @ V  (A-frags LDS.64 via pi layout; V rows logical)
#pragma unroll
        for (int kk = 0; kk < 64; kk += 8) {
            uint32_t af[4][4], bf[2][2];
#pragma unroll
            for (int mt = 0; mt < 4; mt++) {
                int r0 = warpM * 64 + mt * 16 + g;
                float2 a0 = *(const float2*)&Ps[r0 * FP_ST + kk + 2 * t];
                float2 a1 = *(const float2*)&Ps[(r0 + 8) * FP_ST + kk + 2 * t];
                af[mt][0] = fbits(a0.x); af[mt][1] = fbits(a1.x);
                af[mt][2] = fbits(a0.y); af[mt][3] = fbits(a1.y);
            }
#pragma unroll
            for (int nt = 0; nt < 2; nt++) {
                int n0 = warpN * 16 + nt * 8 + g;
                bf[nt][0] = fbits(Vb[(kk + t) * FV_ST + n0]);
                bf[nt][1] = fbits(Vb[(kk + t + 4) * FV_ST + n0]);
            }
#pragma unroll
            for (int mt = 0; mt < 4; mt++)
#pragma unroll
                for (int nt = 0; nt < 2; nt++)
                    mma_tf32(o[mt][nt], af[mt], bf[nt]);
        }

        __syncthreads();
        if (c + 1 < ntiles) { issueV(c + 1, F_B); CP_COMMIT(); }
    }

    // write O to ctx [B,S,H*DH] (d already pi-permuted via V; out-proj reads raw)
#pragma unroll
    for (int mt = 0; mt < 4; mt++) {
#pragma unroll
        for (int nt = 0; nt < 2; nt++) {
            int s0 = qt * 128 + warpM * 64 + mt * 16 + g;
            int d0 = warpN * 16 + nt * 8 + 2 * t;
#pragma unroll
            for (int half = 0; half < 2; half++) {
                int s = s0 + half * 8;
                size_t base = ((size_t)b * Sn + s) * Dn + h * DHn + d0;
                ctx[base] = tf32r(o[mt][nt][half * 2 + 0]);
                ctx[base + 1] = tf32r(o[mt][nt][half * 2 + 1]);
            }
        }
    }
}

// ---------------------------------------------------------------------------
// Launch
// ---------------------------------------------------------------------------
extern "C" void kernel_launch(void* const* d_in, const int* in_sizes, int n_in,
                              void* d_out, int out_size)
{
    const float* Q  = (const float*)d_in[0];
    const float* K  = (const float*)d_in[1];
    const float* V  = (const float*)d_in[2];
    const float* wq = (const float*)d_in[4];
    const float* bq = (const float*)d_in[5];
    const float* wk = (const float*)d_in[6];
    const float* bk = (const float*)d_in[7];
    const float* wv = (const float*)d_in[8];
    const float* bv = (const float*)d_in[9];
    const float* wo = (const float*)d_in[10];
    const float* bo = (const float*)d_in[11];

    float* out = (float*)d_out;

    float* attn;
    if ((size_t)out_size >= OUT_ELEMS + ATTN_ELEMS) {
        attn = out + OUT_ELEMS;
    } else {
        void* p = nullptr;
        cudaGetSymbolAddress(&p, g_attn_scratch);
        attn = (float*)p;
    }

    float *gq, *gk, *gv, *gctx, *gqc, *gkc, *gvc, *gwc;
    {
        void* p;
        cudaGetSymbolAddress(&p, g_q);   gq   = (float*)p;
        cudaGetSymbolAddress(&p, g_k);   gk   = (float*)p;
        cudaGetSymbolAddress(&p, g_v);   gv   = (float*)p;
        cudaGetSymbolAddress(&p, g_ctx); gctx = (float*)p;
        cudaGetSymbolAddress(&p, g_qc);  gqc  = (float*)p;
        cudaGetSymbolAddress(&p, g_kc);  gkc  = (float*)p;
        cudaGetSymbolAddress(&p, g_vc);  gvc  = (float*)p;
        cudaGetSymbolAddress(&p, g_wc);  gwc  = (float*)p;
    }
    float* wtq = gwc;
    float* wtk = gwc + (size_t)Dn * Dn;
    float* wtv = gwc + 2 * (size_t)Dn * Dn;
    float* wto = gwc + 3 * (size_t)Dn * Dn;

    cudaFuncSetAttribute(tf32_gemm_kernel,
                         cudaFuncAttributeMaxDynamicSharedMemorySize, GEMM_SMEM);
    cudaFuncSetAttribute(fused_attn_kernel,
                         cudaFuncAttributeMaxDynamicSharedMemorySize, FUSED_SMEM);

    // pre-process: round + k-permute inputs (1 launch); transpose weights (1 launch)
    const int n8_big = (Mn * Dn) / 8;      // 1,048,576
    dim3 rp_grid((n8_big + 255) / 256, 1, 3);
    round_perm3_kernel<<<rp_grid, 256>>>(Q, K, V, gqc, gkc, gvc, n8_big);
    dim3 tg(Dn / 32, Dn / 32, 4), tb(32, 8);
    wtrans4_kernel<<<tg, tb>>>(wq, wk, wv, wo, wtq, wtk, wtv, wto);

    // QKV projections in one launch (grid.z selects which)
    dim3 gqkv(Dn / 128, Mn / 128, 3);   // (8, 64, 3)
    tf32_gemm_kernel<<<gqkv, 256, GEMM_SMEM>>>(
        gqc, gkc, gvc, wtq, wtk, wtv, bq, bk, bv, gq, gk, gv, 1);

    fused_attn_kernel<<<dim3(NQT, BHn), 256, FUSED_SMEM>>>(gq, gk, gv, attn, gctx);

    // output projection
    dim3 go(Dn / 128, Mn / 128, 1);
    tf32_gemm_kernel<<<go, 256, GEMM_SMEM>>>(
        gctx, gctx, gctx, wto, wto, wto, bo, bo, bo, out, out, out, 0);
}